// round 16
// baseline (speedup 1.0000x reference)
#include <cuda_runtime.h>
#include <cuda_bf16.h>
#include <math.h>

// ---------------- problem constants ----------------
#define BB   128
#define TT   256
#define EE   256
#define H2   256
#define G4H  1024
#define NT   76
#define START_IDX 74
#define STOP_IDX  75
#define NEGV (-10000.0f)

// ---------------- scratch ----------------
__device__ __align__(16) float g_xw[(size_t)2 * BB * TT * G4H];   // xw[d][m][n]
__device__ __align__(16) float g_lstm[(size_t)BB * TT * 512];     // [b][t][dir*256+k]
__device__ __align__(16) float g_feats[(size_t)BB * TT * NT];
// W3[d][ks(8)][kk(256)][kl(32)][g(4)]  (cluster-8 layout)
__device__ __align__(16) float g_W3[(size_t)2 * 8 * 256 * 32 * 4];

// ---------------- f32x2 helpers ----------------
typedef unsigned long long u64;

__device__ __forceinline__ u64 pk2(float lo, float hi) {
    u64 r; asm("mov.b64 %0, {%1, %2};" : "=l"(r) : "f"(lo), "f"(hi)); return r;
}
__device__ __forceinline__ void fma2(u64& d, u64 a, u64 b) {
    asm("fma.rn.f32x2 %0, %1, %2, %0;" : "+l"(d) : "l"(a), "l"(b));
}
__device__ __forceinline__ float2 upk2(u64 v) {
    float2 r; asm("mov.b64 {%0, %1}, %2;" : "=f"(r.x), "=f"(r.y) : "l"(v)); return r;
}
__device__ __forceinline__ float sigm(float x) {
    return 1.0f / (1.0f + expf(-x));
}
__device__ __forceinline__ unsigned smem_u32(const void* p) {
    unsigned a;
    asm("{ .reg .u64 t; cvta.to.shared.u64 t, %1; cvt.u32.u64 %0, t; }"
        : "=r"(a) : "l"(p));
    return a;
}
__device__ __forceinline__ void dsmem_st32(unsigned laddr, int rank, float v) {
    unsigned ra;
    asm volatile("mapa.shared::cluster.u32 %0, %1, %2;" : "=r"(ra) : "r"(laddr), "r"(rank));
    asm volatile("st.shared::cluster.b32 [%0], %1;" :: "r"(ra), "f"(v) : "memory");
}
__device__ __forceinline__ void cpa16(unsigned saddr, const float* gptr) {
    asm volatile("cp.async.cg.shared.global [%0], [%1], 16;"
                 :: "r"(saddr), "l"(gptr) : "memory");
}
#define CP_COMMIT() asm volatile("cp.async.commit_group;" ::: "memory")
#define CP_WAIT(n)  asm volatile("cp.async.wait_group %0;" :: "n"(n) : "memory")

// ---------------- kernel -1: no-op (keeps ncu capture slot on lstm) ----------------
__global__ void noop_kernel() {}

// ---------------- kernel 0: transpose Whh -> g_W3 (ks=8 slices of 32) ----------------
__global__ void transpose_whh_kernel(const float* __restrict__ Whh_f,
                                     const float* __restrict__ Whh_b) {
    size_t idx = (size_t)blockIdx.x * blockDim.x + threadIdx.x;
    const size_t total = (size_t)2 * 1024 * 256;
    if (idx >= total) return;
    int kk  = (int)(idx & 255);
    size_t r = idx >> 8;
    int row = (int)(r & 1023);
    int d   = (int)(r >> 10);
    int g  = row >> 8;
    int k  = row & 255;
    int ks = k >> 5;        // 8 slices of 32 units
    int kl = k & 31;
    const float* W = d ? Whh_b : Whh_f;
    g_W3[((((size_t)(d * 8 + ks)) * 256 + kk) * 32 + kl) * 4 + g] =
        W[(size_t)row * 256 + kk];
}

// ---------------- kernel 1: pre-GEMM v4 (unchanged; near FFMA2 floor) ----------------
#define PGM 128
#define PGN 64
__global__ void __launch_bounds__(256, 2) pregemm_kernel(
    const int*   __restrict__ ids,
    const float* __restrict__ emb,
    const float* __restrict__ Wih_f, const float* __restrict__ Wih_b,
    const float* __restrict__ bih_f, const float* __restrict__ bhh_f,
    const float* __restrict__ bih_b, const float* __restrict__ bhh_b)
{
    extern __shared__ __align__(16) float sm[];
    float* As = sm;
    float* Bs = sm + 128 * 128;
    __shared__ int ids_s[PGM];

    const int d = blockIdx.z;
    const float* __restrict__ Wih = d ? Wih_b : Wih_f;
    const float* __restrict__ b1  = d ? bih_b : bih_f;
    const float* __restrict__ b2  = d ? bhh_b : bhh_f;

    const int m0 = blockIdx.y * PGM;
    const int n0 = blockIdx.x * PGN;
    const int tid = threadIdx.x;

    if (tid < PGM) ids_s[tid] = ids[m0 + tid];
    __syncthreads();

    const int tx = tid & 15;
    const int ty = tid >> 4;

    float bsum[4];
#pragma unroll
    for (int j = 0; j < 4; j++) {
        int n = n0 + tx * 4 + j;
        bsum[j] = b1[n] + b2[n];
    }

    u64 acc[4][4];
#pragma unroll
    for (int p = 0; p < 4; p++)
#pragma unroll
        for (int j = 0; j < 4; j++) acc[p][j] = 0ULL;

    const float* ap = As + ty * 8;
    const float* bp = Bs + tx * 4;

    const int ar  = tid >> 1;
    const int ac0 = (tid & 1) * 64;
    const float* asrc = emb + (size_t)ids_s[ar] * 256 + ac0;
    const int br  = tid >> 2;
    const int bc0 = (tid & 3) * 32;
    const float* bsrc = Wih + (size_t)(n0 + br) * 256 + bc0;

#pragma unroll
    for (int h = 0; h < 2; h++) {
        {
            const float* src = asrc + h * 128;
#pragma unroll
            for (int j = 0; j < 16; j++) {
                float4 v = *(const float4*)(src + j * 4);
                int c = ac0 + j * 4;
                As[(c + 0) * 128 + ar] = v.x;
                As[(c + 1) * 128 + ar] = v.y;
                As[(c + 2) * 128 + ar] = v.z;
                As[(c + 3) * 128 + ar] = v.w;
            }
        }
        {
            const float* src = bsrc + h * 128;
#pragma unroll
            for (int j = 0; j < 8; j++) {
                float4 v = *(const float4*)(src + j * 4);
                int c = bc0 + j * 4;
                Bs[(c + 0) * 64 + br] = v.x;
                Bs[(c + 1) * 64 + br] = v.y;
                Bs[(c + 2) * 64 + br] = v.z;
                Bs[(c + 3) * 64 + br] = v.w;
            }
        }
        __syncthreads();

#pragma unroll 4
        for (int kk = 0; kk < 128; kk++) {
            ulonglong2 a01 = *(const ulonglong2*)(ap + kk * 128);
            ulonglong2 a23 = *(const ulonglong2*)(ap + kk * 128 + 4);
            float4 b = *(const float4*)(bp + kk * 64);
            u64 bd[4];
            bd[0] = pk2(b.x, b.x); bd[1] = pk2(b.y, b.y);
            bd[2] = pk2(b.z, b.z); bd[3] = pk2(b.w, b.w);
#pragma unroll
            for (int j = 0; j < 4; j++) {
                fma2(acc[0][j], a01.x, bd[j]);
                fma2(acc[1][j], a01.y, bd[j]);
                fma2(acc[2][j], a23.x, bd[j]);
                fma2(acc[3][j], a23.y, bd[j]);
            }
        }
        __syncthreads();
    }

#pragma unroll
    for (int p = 0; p < 4; p++) {
        float2 v0 = upk2(acc[p][0]);
        float2 v1 = upk2(acc[p][1]);
        float2 v2 = upk2(acc[p][2]);
        float2 v3 = upk2(acc[p][3]);
        int mA = m0 + ty * 8 + 2 * p;
        float4 rA = {v0.x + bsum[0], v1.x + bsum[1], v2.x + bsum[2], v3.x + bsum[3]};
        float4 rB = {v0.y + bsum[0], v1.y + bsum[1], v2.y + bsum[2], v3.y + bsum[3]};
        *(float4*)(g_xw + ((size_t)d * (BB * TT) + mA) * G4H + n0 + tx * 4) = rA;
        *(float4*)(g_xw + ((size_t)d * (BB * TT) + mA + 1) * G4H + n0 + tx * 4) = rB;
    }
}

// ---------------- kernel 2: recurrent LSTM v15 ----------------
// cluster-8 k-split, G=8, 256 threads, **2 CTAs/SM** (107KB smem, <=128 regs).
// Thread (kl=tid>>3 in 0..31, bh=tid&7): 1 batch, 1 unit kg=rank*32+kl.
// Resident weights kk 0..95 (49KB); kk 96..255 streamed in four 40-kk chunks
// via 2 cp.async buffers (R10 pattern). Co-resident CTA from another cluster
// fills all stall slots (barrier waits, CP_WAITs, LDS latency).
// Accumulation kk = 0..255 ascending -> bitwise-identical results.
#define HROW 260
#define RK8  96
#define CH8  40

// accumulate n4 kk for one batch row; weight stride 128 floats/kk
__device__ __forceinline__ void wh_acc8(
    const float* __restrict__ wbase, const float* __restrict__ hp,
    int n4, int kl, u64& aif, u64& ago)
{
#pragma unroll 4
    for (int kk4 = 0; kk4 < n4; kk4 += 4) {
        float4 h4 = *(const float4*)(hp + kk4);
        float hv[4] = {h4.x, h4.y, h4.z, h4.w};
#pragma unroll
        for (int u = 0; u < 4; u++) {
            ulonglong2 w = *(const ulonglong2*)(wbase + (kk4 + u) * 128 + kl * 4);
            u64 hd = pk2(hv[u], hv[u]);
            fma2(aif, w.x, hd);
            fma2(ago, w.y, hd);
        }
    }
}

// fill one 40-kk chunk (5120 floats = 1280 float4): 5 cpa16/thread
__device__ __forceinline__ void fill40(unsigned sbuf, const float* gsrc, int tid) {
#pragma unroll
    for (int i = 0; i < 5; i++)
        cpa16(sbuf + (unsigned)(tid + i * 256) * 16, gsrc + (size_t)(tid + i * 256) * 4);
}

__global__ void __cluster_dims__(8, 1, 1) __launch_bounds__(256, 2)
lstm_rec_kernel(const float* __restrict__ h0, const float* __restrict__ c0)
{
    extern __shared__ __align__(16) float sm2[];
    float* smw  = sm2;                       // resident kk 0..95 (12288 f)
    float* stgA = sm2 + RK8 * 128;           // 40-kk buffer A (5120 f)
    float* stgB = stgA + CH8 * 128;          // 40-kk buffer B (5120 f)
    float* hq   = stgB + CH8 * 128;          // h[2][8][HROW] (4160 f)

    const int cid  = blockIdx.x >> 3;
    const int rank = blockIdx.x & 7;
    const int d    = cid >> 4;
    const int grp  = cid & 15;
    const int b0   = grp * 8;
    const int tid  = threadIdx.x;
    const int kl   = tid >> 3;      // 0..31
    const int bh   = tid & 7;       // 0..7
    const int kg   = rank * 32 + kl;

    const float* __restrict__ wsrc =
        g_W3 + ((size_t)(d * 8 + rank)) * (256 * 32 * 4);

    // preload resident kk 0..95 (3072 float4, 12/thread)
    {
        const float4* src = (const float4*)wsrc;
        float4* dst = (float4*)smw;
#pragma unroll
        for (int j = 0; j < 12; j++)
            dst[tid + j * 256] = src[tid + j * 256];
    }

    // init h and c
    for (int idx = tid; idx < 8 * 256; idx += 256) {
        int bi = idx >> 8;
        int u  = idx & 255;
        hq[(0 * 8 + bi) * HROW + u] = h0[((size_t)d * BB + b0 + bi) * H2 + u];
    }
    float c_reg = c0[((size_t)d * BB + b0 + bh) * H2 + kg];
    __syncthreads();

    // xw registers for step 0
    float xr[4];
    {
        const int t0 = d ? (TT - 1) : 0;
        const float* xp = g_xw + (((size_t)d * BB + b0 + bh) * TT + t0) * G4H;
        xr[0] = xp[kg];
        xr[1] = xp[256 + kg];
        xr[2] = xp[512 + kg];
        xr[3] = xp[768 + kg];
    }

    const unsigned sA = smem_u32(stgA);
    const unsigned sB = smem_u32(stgB);
    const float* c0src = wsrc + (size_t)RK8 * 128;            // kk 96..135
    const float* c1src = wsrc + (size_t)(RK8 + CH8) * 128;    // kk 136..175
    const float* c2src = wsrc + (size_t)(RK8 + 2 * CH8) * 128;// kk 176..215
    const float* c3src = wsrc + (size_t)(RK8 + 3 * CH8) * 128;// kk 216..255

    // first chunk-0 fill, a full resident-compute ahead
    fill40(sA, c0src, tid); CP_COMMIT();

    for (int step = 0; step < TT; step++) {
        const int t   = d ? (TT - 1 - step) : step;
        const int cur = step & 1;
        const int nxt = cur ^ 1;

        // head fills: A<-c0 (prev tail / pre-loop), B<-c1
        if (step > 0) { fill40(sA, c0src, tid); CP_COMMIT(); }
        fill40(sB, c1src, tid); CP_COMMIT();

        u64 aif = pk2(xr[0], xr[1]);
        u64 ago = pk2(xr[2], xr[3]);

        // xw prefetch for NEXT step at the head (full-step DRAM cover)
        if (step + 1 < TT) {
            const int tn = d ? (TT - 2 - step) : (step + 1);
            const float* xp = g_xw + (((size_t)d * BB + b0 + bh) * TT + tn) * G4H;
            xr[0] = xp[kg];
            xr[1] = xp[256 + kg];
            xr[2] = xp[512 + kg];
            xr[3] = xp[768 + kg];
        }

        const float* hr = hq + (cur * 8 + bh) * HROW;

        // kk 0..95 from resident smem
        wh_acc8(smw, hr, RK8, kl, aif, ago);

        CP_WAIT(1); __syncthreads();                 // c0 ready
        wh_acc8(stgA, hr + RK8, CH8, kl, aif, ago);
        __syncthreads();                             // A free
        fill40(sA, c2src, tid); CP_COMMIT();         // A<-c2

        CP_WAIT(1); __syncthreads();                 // c1 ready
        wh_acc8(stgB, hr + RK8 + CH8, CH8, kl, aif, ago);
        __syncthreads();                             // B free
        fill40(sB, c3src, tid); CP_COMMIT();         // B<-c3

        CP_WAIT(1); __syncthreads();                 // c2 ready
        wh_acc8(stgA, hr + RK8 + 2 * CH8, CH8, kl, aif, ago);

        CP_WAIT(0); __syncthreads();                 // c3 ready
        wh_acc8(stgB, hr + RK8 + 3 * CH8, CH8, kl, aif, ago);

        // gates, state update, h broadcast to the 8 cluster ranks
        {
            float2 gif = upk2(aif);
            float2 ggo = upk2(ago);
            float ig = sigm(gif.x);
            float fg = sigm(gif.y);
            float gg = tanhf(ggo.x);
            float og = sigm(ggo.y);
            float cn = fg * c_reg + ig * gg;
            c_reg = cn;
            float hn = og * tanhf(cn);
            unsigned laddr = smem_u32(&hq[(nxt * 8 + bh) * HROW + kg]);
#pragma unroll
            for (int r = 0; r < 8; r++) dsmem_st32(laddr, r, hn);
            g_lstm[(((size_t)(b0 + bh)) * TT + t) * 512 + d * 256 + kg] = hn;
        }

        asm volatile("barrier.cluster.arrive.aligned;" ::: "memory");
        asm volatile("barrier.cluster.wait.aligned;" ::: "memory");
    }
}

// ---------------- kernel 3: feats v2 (unchanged) ----------------
__global__ void __launch_bounds__(256) feats_kernel(
    const float* __restrict__ W_out, const float* __restrict__ b_out)
{
    const int m0  = blockIdx.x * 64;
    const int tid = threadIdx.x;
    const int rg  = tid >> 4;
    const int jg  = tid & 15;

    __shared__ __align__(16) float Wt[64][80];
    __shared__ __align__(16) float Xs[64][68];

    u64 acc[4][3];
#pragma unroll
    for (int i = 0; i < 4; i++)
#pragma unroll
        for (int p = 0; p < 3; p++) acc[i][p] = 0ULL;

    for (int k0 = 0; k0 < 512; k0 += 64) {
        for (int idx = tid; idx < 64 * 80; idx += 256) {
            int kk  = idx / 80;
            int tag = idx - kk * 80;
            Wt[kk][tag] = (tag < NT) ? W_out[(size_t)tag * 512 + k0 + kk] : 0.0f;
        }
#pragma unroll
        for (int i = 0; i < 4; i++) {
            int idx = tid + i * 256;
            int row = idx >> 4;
            int c4  = (idx & 15) * 4;
            *(float4*)&Xs[row][c4] =
                *(const float4*)(g_lstm + (size_t)(m0 + row) * 512 + k0 + c4);
        }
        __syncthreads();

#pragma unroll 2
        for (int kk4 = 0; kk4 < 64; kk4 += 4) {
            float xv[4][4];
#pragma unroll
            for (int i = 0; i < 4; i++) {
                float4 v = *(const float4*)&Xs[rg * 4 + i][kk4];
                xv[i][0] = v.x; xv[i][1] = v.y; xv[i][2] = v.z; xv[i][3] = v.w;
            }
#pragma unroll
            for (int u = 0; u < 4; u++) {
                u64 w0 = *(const u64*)&Wt[kk4 + u][2 * jg];
                u64 w1 = *(const u64*)&Wt[kk4 + u][2 * jg + 32];
                u64 w2 = *(const u64*)&Wt[kk4 + u][2 * jg + 64];
#pragma unroll
                for (int i = 0; i < 4; i++) {
                    u64 xd = pk2(xv[i][u], xv[i][u]);
                    fma2(acc[i][0], xd, w0);
                    fma2(acc[i][1], xd, w1);
                    fma2(acc[i][2], xd, w2);
                }
            }
        }
        __syncthreads();
    }

#pragma unroll
    for (int i = 0; i < 4; i++) {
        int row = m0 + rg * 4 + i;
#pragma unroll
        for (int p = 0; p < 3; p++) {
            int tag = 2 * jg + p * 32;
            if (tag + 1 < NT) {
                float2 v = upk2(acc[i][p]);
                g_feats[(size_t)row * NT + tag]     = v.x + b_out[tag];
                g_feats[(size_t)row * NT + tag + 1] = v.y + b_out[tag + 1];
            }
        }
    }
}

// ---------------- kernel 4: Viterbi v2 (unchanged) ----------------
__global__ void __launch_bounds__(320) viterbi_kernel(
    const float* __restrict__ trans, float* __restrict__ out)
{
    const int b    = blockIdx.x;
    const int tid  = threadIdx.x;
    const int nt   = tid >> 2;
    const int s    = tid & 3;

    __shared__ float trans_s[NT * NT];
    __shared__ float fv0[NT], fv1[NT];
    __shared__ unsigned char bp[TT][NT];

    for (int i = tid; i < NT * NT; i += blockDim.x) trans_s[i] = trans[i];
    if (tid < NT) fv0[tid] = (tid == START_IDX) ? 0.0f : NEGV;
    __syncthreads();

    float tr[19];
    if (nt < NT) {
#pragma unroll
        for (int i = 0; i < 19; i++)
            tr[i] = trans_s[nt * NT + s * 19 + i];
    }

    const float* __restrict__ feats_b = g_feats + (size_t)b * TT * NT;

    for (int t = 0; t < TT; t++) {
        float* fv  = (t & 1) ? fv1 : fv0;
        float* fvn = (t & 1) ? fv0 : fv1;

        float best = -INFINITY;
        int arg = s * 19;
        if (nt < NT) {
#pragma unroll
            for (int i = 0; i < 19; i++) {
                float v = fv[s * 19 + i] + tr[i];
                if (v > best) { best = v; arg = s * 19 + i; }
            }
        }
#pragma unroll
        for (int dlt = 2; dlt >= 1; dlt >>= 1) {
            float ov = __shfl_down_sync(0xffffffffu, best, dlt);
            int   oa = __shfl_down_sync(0xffffffffu, arg,  dlt);
            if (ov > best) { best = ov; arg = oa; }
        }
        if (s == 0 && nt < NT) {
            fvn[nt] = best + feats_b[t * NT + nt];
            bp[t][nt] = (unsigned char)arg;
        }
        __syncthreads();
    }

    if (tid == 0) {
        float* fvF = fv0;
        float best = -INFINITY;
        int arg = 0;
        for (int j = 0; j < NT; j++) {
            float sc = fvF[j] + trans_s[STOP_IDX * NT + j];
            if (sc > best) { best = sc; arg = j; }
        }
        out[b] = best;
        float* po = out + BB + (size_t)b * TT;
        int tag = arg;
        po[TT - 1] = (float)tag;
        for (int t = TT - 1; t >= 1; t--) {
            tag = bp[t][tag];
            po[t - 1] = (float)tag;
        }
    }
}

// ---------------- launch ----------------
extern "C" void kernel_launch(void* const* d_in, const int* in_sizes, int n_in,
                              void* d_out, int out_size) {
    const int*   ids    = (const int*)  d_in[0];
    const float* emb    = (const float*)d_in[1];
    const float* Wih_f  = (const float*)d_in[2];
    const float* Whh_f  = (const float*)d_in[3];
    const float* bih_f  = (const float*)d_in[4];
    const float* bhh_f  = (const float*)d_in[5];
    const float* Wih_b  = (const float*)d_in[6];
    const float* Whh_b  = (const float*)d_in[7];
    const float* bih_b  = (const float*)d_in[8];
    const float* bhh_b  = (const float*)d_in[9];
    const float* h0     = (const float*)d_in[10];
    const float* c0     = (const float*)d_in[11];
    const float* W_out  = (const float*)d_in[12];
    const float* b_out  = (const float*)d_in[13];
    const float* trans  = (const float*)d_in[14];
    float* out = (float*)d_out;

    (void)in_sizes; (void)n_in; (void)out_size;

    // keeps the fixed ncu capture slot on lstm_rec
    noop_kernel<<<1, 32>>>();

    {
        const size_t total = (size_t)2 * 1024 * 256;
        transpose_whh_kernel<<<(unsigned)((total + 255) / 256), 256>>>(Whh_f, Whh_b);
    }
    {
        const int smem_bytes = (128 * 128 + 128 * 64) * 4;   // 96 KB
        cudaFuncSetAttribute(pregemm_kernel,
                             cudaFuncAttributeMaxDynamicSharedMemorySize, smem_bytes);
        dim3 grid(G4H / PGN, (BB * TT) / PGM, 2);
        pregemm_kernel<<<grid, 256, smem_bytes>>>(ids, emb, Wih_f, Wih_b,
                                                  bih_f, bhh_f, bih_b, bhh_b);
    }
    {
        // 49KB resident + 2x20.5KB staging + 16.6KB h = ~107KB -> 2 CTAs/SM
        const int lstm_smem = (RK8 * 128 + 2 * CH8 * 128 + 2 * 8 * HROW) * 4;
        cudaFuncSetAttribute(lstm_rec_kernel,
                             cudaFuncAttributeMaxDynamicSharedMemorySize, lstm_smem);
        lstm_rec_kernel<<<256, 256, lstm_smem>>>(h0, c0);
    }
    feats_kernel<<<(BB * TT) / 64, 256>>>(W_out, b_out);
    viterbi_kernel<<<BB, 320>>>(trans, out);
}

// round 17
// speedup vs baseline: 1.2917x; 1.2917x over previous
#include <cuda_runtime.h>
#include <cuda_bf16.h>
#include <math.h>

// ---------------- problem constants ----------------
#define BB   128
#define TT   256
#define EE   256
#define H2   256
#define G4H  1024
#define NT   76
#define START_IDX 74
#define STOP_IDX  75
#define NEGV (-10000.0f)

// ---------------- scratch ----------------
__device__ __align__(16) float g_xw[(size_t)2 * BB * TT * G4H];   // xw[d][m][n]
__device__ __align__(16) float g_lstm[(size_t)BB * TT * 512];     // [b][t][dir*256+k]
__device__ __align__(16) float g_feats[(size_t)BB * TT * NT];
// W3[d][ks(4)][kk(256)][kl(64)][g(4)]  (cluster-4 layout)
__device__ __align__(16) float g_W3[(size_t)2 * 4 * 256 * 64 * 4];

// ---------------- f32x2 helpers ----------------
typedef unsigned long long u64;

__device__ __forceinline__ u64 pk2(float lo, float hi) {
    u64 r; asm("mov.b64 %0, {%1, %2};" : "=l"(r) : "f"(lo), "f"(hi)); return r;
}
__device__ __forceinline__ void fma2(u64& d, u64 a, u64 b) {
    asm("fma.rn.f32x2 %0, %1, %2, %0;" : "+l"(d) : "l"(a), "l"(b));
}
__device__ __forceinline__ float2 upk2(u64 v) {
    float2 r; asm("mov.b64 {%0, %1}, %2;" : "=f"(r.x), "=f"(r.y) : "l"(v)); return r;
}
__device__ __forceinline__ float sigm(float x) {
    return 1.0f / (1.0f + expf(-x));
}
__device__ __forceinline__ unsigned smem_u32(const void* p) {
    unsigned a;
    asm("{ .reg .u64 t; cvta.to.shared.u64 t, %1; cvt.u32.u64 %0, t; }"
        : "=r"(a) : "l"(p));
    return a;
}
__device__ __forceinline__ void dsmem_st32(unsigned laddr, int rank, float v) {
    unsigned ra;
    asm volatile("mapa.shared::cluster.u32 %0, %1, %2;" : "=r"(ra) : "r"(laddr), "r"(rank));
    asm volatile("st.shared::cluster.b32 [%0], %1;" :: "r"(ra), "f"(v) : "memory");
}
__device__ __forceinline__ void cpa16(unsigned saddr, const float* gptr) {
    asm volatile("cp.async.cg.shared.global [%0], [%1], 16;"
                 :: "r"(saddr), "l"(gptr) : "memory");
}
#define CP_COMMIT() asm volatile("cp.async.commit_group;" ::: "memory")
#define CP_WAIT(n)  asm volatile("cp.async.wait_group %0;" :: "n"(n) : "memory")

// ---------------- kernel -1: no-op (keeps ncu capture slot on lstm) ----------------
__global__ void noop_kernel() {}

// ---------------- kernel 0: transpose Whh -> g_W3 ----------------
__global__ void transpose_whh_kernel(const float* __restrict__ Whh_f,
                                     const float* __restrict__ Whh_b) {
    size_t idx = (size_t)blockIdx.x * blockDim.x + threadIdx.x;
    const size_t total = (size_t)2 * 1024 * 256;
    if (idx >= total) return;
    int kk  = (int)(idx & 255);
    size_t r = idx >> 8;
    int row = (int)(r & 1023);
    int d   = (int)(r >> 10);
    int g  = row >> 8;
    int k  = row & 255;
    int ks = k >> 6;
    int kl = k & 63;
    const float* W = d ? Whh_b : Whh_f;
    g_W3[((((size_t)(d * 4 + ks)) * 256 + kk) * 64 + kl) * 4 + g] =
        W[(size_t)row * 256 + kk];
}

// ---------------- kernel 1: pre-GEMM v5 (48KB smem -> 3 CTAs/SM) ----------------
// CTA tile 128m x 64n, K in FOUR 64-chunks (As[64][128]=32KB, Bs[64][64]=16KB).
// Accumulation kk = 0..255 ascending (bitwise-identical to prior rounds).
#define PGM 128
#define PGN 64
__global__ void __launch_bounds__(256, 3) pregemm_kernel(
    const int*   __restrict__ ids,
    const float* __restrict__ emb,
    const float* __restrict__ Wih_f, const float* __restrict__ Wih_b,
    const float* __restrict__ bih_f, const float* __restrict__ bhh_f,
    const float* __restrict__ bih_b, const float* __restrict__ bhh_b)
{
    extern __shared__ __align__(16) float sm[];
    float* As = sm;                  // [kk 0..63][m 0..127]  32KB
    float* Bs = sm + 64 * 128;       // [kk 0..63][n 0..63]   16KB
    __shared__ int ids_s[PGM];

    const int d = blockIdx.z;
    const float* __restrict__ Wih = d ? Wih_b : Wih_f;
    const float* __restrict__ b1  = d ? bih_b : bih_f;
    const float* __restrict__ b2  = d ? bhh_b : bhh_f;

    const int m0 = blockIdx.y * PGM;
    const int n0 = blockIdx.x * PGN;
    const int tid = threadIdx.x;

    if (tid < PGM) ids_s[tid] = ids[m0 + tid];
    __syncthreads();

    const int tx = tid & 15;
    const int ty = tid >> 4;

    float bsum[4];
#pragma unroll
    for (int j = 0; j < 4; j++) {
        int n = n0 + tx * 4 + j;
        bsum[j] = b1[n] + b2[n];
    }

    u64 acc[4][4];
#pragma unroll
    for (int p = 0; p < 4; p++)
#pragma unroll
        for (int j = 0; j < 4; j++) acc[p][j] = 0ULL;

    const float* ap = As + ty * 8;
    const float* bp = Bs + tx * 4;

    // A staging: row ar=tid>>1, 32 cols at (tid&1)*32 (8 float4)
    const int ar  = tid >> 1;
    const int ac0 = (tid & 1) * 32;
    const float* asrc = emb + (size_t)ids_s[ar] * 256 + ac0;
    // B staging: row br=tid>>2, 16 cols at (tid&3)*16 (4 float4)
    const int br  = tid >> 2;
    const int bc0 = (tid & 3) * 16;
    const float* bsrc = Wih + (size_t)(n0 + br) * 256 + bc0;

#pragma unroll
    for (int ch = 0; ch < 4; ch++) {
        {
            const float* src = asrc + ch * 64;
#pragma unroll
            for (int j = 0; j < 8; j++) {
                float4 v = *(const float4*)(src + j * 4);
                int c = ac0 + j * 4;
                As[(c + 0) * 128 + ar] = v.x;
                As[(c + 1) * 128 + ar] = v.y;
                As[(c + 2) * 128 + ar] = v.z;
                As[(c + 3) * 128 + ar] = v.w;
            }
        }
        {
            const float* src = bsrc + ch * 64;
#pragma unroll
            for (int j = 0; j < 4; j++) {
                float4 v = *(const float4*)(src + j * 4);
                int c = bc0 + j * 4;
                Bs[(c + 0) * 64 + br] = v.x;
                Bs[(c + 1) * 64 + br] = v.y;
                Bs[(c + 2) * 64 + br] = v.z;
                Bs[(c + 3) * 64 + br] = v.w;
            }
        }
        __syncthreads();

#pragma unroll 4
        for (int kk = 0; kk < 64; kk++) {
            ulonglong2 a01 = *(const ulonglong2*)(ap + kk * 128);
            ulonglong2 a23 = *(const ulonglong2*)(ap + kk * 128 + 4);
            float4 b = *(const float4*)(bp + kk * 64);
            u64 bd[4];
            bd[0] = pk2(b.x, b.x); bd[1] = pk2(b.y, b.y);
            bd[2] = pk2(b.z, b.z); bd[3] = pk2(b.w, b.w);
#pragma unroll
            for (int j = 0; j < 4; j++) {
                fma2(acc[0][j], a01.x, bd[j]);
                fma2(acc[1][j], a01.y, bd[j]);
                fma2(acc[2][j], a23.x, bd[j]);
                fma2(acc[3][j], a23.y, bd[j]);
            }
        }
        __syncthreads();
    }

#pragma unroll
    for (int p = 0; p < 4; p++) {
        float2 v0 = upk2(acc[p][0]);
        float2 v1 = upk2(acc[p][1]);
        float2 v2 = upk2(acc[p][2]);
        float2 v3 = upk2(acc[p][3]);
        int mA = m0 + ty * 8 + 2 * p;
        float4 rA = {v0.x + bsum[0], v1.x + bsum[1], v2.x + bsum[2], v3.x + bsum[3]};
        float4 rB = {v0.y + bsum[0], v1.y + bsum[1], v2.y + bsum[2], v3.y + bsum[3]};
        *(float4*)(g_xw + ((size_t)d * (BB * TT) + mA) * G4H + n0 + tx * 4) = rA;
        *(float4*)(g_xw + ((size_t)d * (BB * TT) + mA + 1) * G4H + n0 + tx * 4) = rB;
    }
}

// ---------------- kernel 2: recurrent LSTM (R10 champion, verbatim) ----------------
// cluster-4 k-split, G=8, 256 threads. Resident kk 0..111 (112KB smem);
// kk 112..255 streamed in three 48-kk chunks via 2x48KB cp.async buffers,
// with chunk fills issued a full compute-phase (or a full step) ahead.
// Accumulation kk = 0..255 ascending -> bitwise-identical results.
#define HROW 260
#define RK   112

__device__ __forceinline__ void wh_accum(
    const float* __restrict__ wbase, const float* __restrict__ h0p,
    const float* __restrict__ h1p, int n4, int kl, u64* aif, u64* ago)
{
#pragma unroll 4
    for (int kk4 = 0; kk4 < n4; kk4 += 4) {
        float4 h4a = *(const float4*)(h0p + kk4);
        float4 h4b = *(const float4*)(h1p + kk4);
        float ha[4] = {h4a.x, h4a.y, h4a.z, h4a.w};
        float hb[4] = {h4b.x, h4b.y, h4b.z, h4b.w};
#pragma unroll
        for (int u = 0; u < 4; u++) {
            ulonglong2 w = *(const ulonglong2*)(wbase + (kk4 + u) * 256 + kl * 4);
            u64 hda = pk2(ha[u], ha[u]);
            u64 hdb = pk2(hb[u], hb[u]);
            fma2(aif[0], w.x, hda);
            fma2(ago[0], w.y, hda);
            fma2(aif[1], w.x, hdb);
            fma2(ago[1], w.y, hdb);
        }
    }
}

// fill one 48-kk chunk (12288 floats = 3072 float4) via cp.async
__device__ __forceinline__ void fill48(unsigned sbuf, const float* gsrc, int tid) {
#pragma unroll
    for (int i = 0; i < 12; i++)
        cpa16(sbuf + (unsigned)(tid + i * 256) * 16, gsrc + (size_t)(tid + i * 256) * 4);
}

__global__ void __cluster_dims__(4, 1, 1) __launch_bounds__(256, 1)
lstm_rec_kernel(const float* __restrict__ h0, const float* __restrict__ c0)
{
    extern __shared__ __align__(16) float sm2[];
    float* smw  = sm2;                       // resident kk 0..111 (28672 f)
    float* stgA = sm2 + RK * 256;            // 48-kk buffer A (12288 f)
    float* stgB = stgA + 48 * 256;           // 48-kk buffer B
    float* hq   = stgB + 48 * 256;           // h[2][8][HROW]

    const int cid  = blockIdx.x >> 2;
    const int rank = blockIdx.x & 3;
    const int d    = cid >> 4;
    const int grp  = cid & 15;
    const int b0   = grp * 8;
    const int tid  = threadIdx.x;
    const int kl   = tid >> 2;      // 0..63
    const int bq   = tid & 3;       // 0..3
    const int kg   = rank * 64 + kl;

    const float* __restrict__ wsrc =
        g_W3 + ((size_t)(d * 4 + rank)) * (256 * 64 * 4);

    // preload resident weight half kk 0..111 (28672 floats = 7168 float4)
    {
        const float4* src = (const float4*)wsrc;
        float4* dst = (float4*)smw;
#pragma unroll
        for (int j = 0; j < 28; j++)
            dst[tid + j * 256] = src[tid + j * 256];
    }

    // init h (plain) and c
#pragma unroll
    for (int bi = 0; bi < 8; bi++)
        hq[(0 * 8 + bi) * HROW + tid] = h0[((size_t)d * BB + b0 + bi) * H2 + tid];
    float c_reg[2];
#pragma unroll
    for (int j = 0; j < 2; j++)
        c_reg[j] = c0[((size_t)d * BB + b0 + bq + 4 * j) * H2 + kg];
    __syncthreads();

    // xw registers, prefetched each step
    float xr[8];
    {
        const int t0 = d ? (TT - 1) : 0;
#pragma unroll
        for (int j = 0; j < 2; j++) {
            const float* xp =
                g_xw + (((size_t)d * BB + b0 + bq + 4 * j) * TT + t0) * G4H;
            xr[j * 4 + 0] = xp[kg];
            xr[j * 4 + 1] = xp[256 + kg];
            xr[j * 4 + 2] = xp[512 + kg];
            xr[j * 4 + 3] = xp[768 + kg];
        }
    }

    const unsigned sA = smem_u32(stgA);
    const unsigned sB = smem_u32(stgB);
    const float* c0src = wsrc + (size_t)112 * 256;   // kk 112..159
    const float* c1src = wsrc + (size_t)160 * 256;   // kk 160..207
    const float* c2src = wsrc + (size_t)208 * 256;   // kk 208..255

    // first chunk-0 fill, a full resident-compute ahead
    fill48(sA, c0src, tid); CP_COMMIT();

    for (int step = 0; step < TT; step++) {
        const int t   = d ? (TT - 1 - step) : step;
        const int cur = step & 1;
        const int nxt = cur ^ 1;

        // head fills: A<-c0 was issued at previous step's tail (or pre-loop);
        // B<-c1 issued here (B's previous contents fully consumed pre-barrier).
        if (step > 0) { fill48(sA, c0src, tid); CP_COMMIT(); }
        fill48(sB, c1src, tid); CP_COMMIT();

        u64 aif[2], ago[2];
        aif[0] = pk2(xr[0], xr[1]); ago[0] = pk2(xr[2], xr[3]);
        aif[1] = pk2(xr[4], xr[5]); ago[1] = pk2(xr[6], xr[7]);

        const float* hr0 = hq + (cur * 8 + bq) * HROW;
        const float* hr1 = hq + (cur * 8 + bq + 4) * HROW;

        // kk 0..111 from resident smem
        wh_accum(smw, hr0, hr1, RK, kl, aif, ago);

        CP_WAIT(1); __syncthreads();                 // c0 ready
        wh_accum(stgA, hr0 + 112, hr1 + 112, 48, kl, aif, ago);
        __syncthreads();                             // A free
        fill48(sA, c2src, tid); CP_COMMIT();         // A<-c2

        CP_WAIT(1); __syncthreads();                 // c1 ready
        wh_accum(stgB, hr0 + 160, hr1 + 160, 48, kl, aif, ago);

        CP_WAIT(0); __syncthreads();                 // c2 ready
        wh_accum(stgA, hr0 + 208, hr1 + 208, 48, kl, aif, ago);

        // prefetch xw for next step (hidden behind tail + cluster barrier)
        if (step + 1 < TT) {
            const int tn = d ? (TT - 2 - step) : (step + 1);
#pragma unroll
            for (int j = 0; j < 2; j++) {
                const float* xp =
                    g_xw + (((size_t)d * BB + b0 + bq + 4 * j) * TT + tn) * G4H;
                xr[j * 4 + 0] = xp[kg];
                xr[j * 4 + 1] = xp[256 + kg];
                xr[j * 4 + 2] = xp[512 + kg];
                xr[j * 4 + 3] = xp[768 + kg];
            }
        }

        // gates, state update, h broadcast to the 4 cluster ranks
#pragma unroll
        for (int j = 0; j < 2; j++) {
            const int bi = bq + 4 * j;
            float2 gif = upk2(aif[j]);
            float2 ggo = upk2(ago[j]);
            float ig = sigm(gif.x);
            float fg = sigm(gif.y);
            float gg = tanhf(ggo.x);
            float og = sigm(ggo.y);
            float cn = fg * c_reg[j] + ig * gg;
            c_reg[j] = cn;
            float hn = og * tanhf(cn);
            unsigned laddr = smem_u32(&hq[(nxt * 8 + bi) * HROW + kg]);
#pragma unroll
            for (int r = 0; r < 4; r++) dsmem_st32(laddr, r, hn);
            g_lstm[(((size_t)(b0 + bi)) * TT + t) * 512 + d * 256 + kg] = hn;
        }

        asm volatile("barrier.cluster.arrive.aligned;" ::: "memory");
        asm volatile("barrier.cluster.wait.aligned;" ::: "memory");
    }
}

// ---------------- kernel 3: feats v2 (unchanged) ----------------
__global__ void __launch_bounds__(256) feats_kernel(
    const float* __restrict__ W_out, const float* __restrict__ b_out)
{
    const int m0  = blockIdx.x * 64;
    const int tid = threadIdx.x;
    const int rg  = tid >> 4;
    const int jg  = tid & 15;

    __shared__ __align__(16) float Wt[64][80];
    __shared__ __align__(16) float Xs[64][68];

    u64 acc[4][3];
#pragma unroll
    for (int i = 0; i < 4; i++)
#pragma unroll
        for (int p = 0; p < 3; p++) acc[i][p] = 0ULL;

    for (int k0 = 0; k0 < 512; k0 += 64) {
        for (int idx = tid; idx < 64 * 80; idx += 256) {
            int kk  = idx / 80;
            int tag = idx - kk * 80;
            Wt[kk][tag] = (tag < NT) ? W_out[(size_t)tag * 512 + k0 + kk] : 0.0f;
        }
#pragma unroll
        for (int i = 0; i < 4; i++) {
            int idx = tid + i * 256;
            int row = idx >> 4;
            int c4  = (idx & 15) * 4;
            *(float4*)&Xs[row][c4] =
                *(const float4*)(g_lstm + (size_t)(m0 + row) * 512 + k0 + c4);
        }
        __syncthreads();

#pragma unroll 2
        for (int kk4 = 0; kk4 < 64; kk4 += 4) {
            float xv[4][4];
#pragma unroll
            for (int i = 0; i < 4; i++) {
                float4 v = *(const float4*)&Xs[rg * 4 + i][kk4];
                xv[i][0] = v.x; xv[i][1] = v.y; xv[i][2] = v.z; xv[i][3] = v.w;
            }
#pragma unroll
            for (int u = 0; u < 4; u++) {
                u64 w0 = *(const u64*)&Wt[kk4 + u][2 * jg];
                u64 w1 = *(const u64*)&Wt[kk4 + u][2 * jg + 32];
                u64 w2 = *(const u64*)&Wt[kk4 + u][2 * jg + 64];
#pragma unroll
                for (int i = 0; i < 4; i++) {
                    u64 xd = pk2(xv[i][u], xv[i][u]);
                    fma2(acc[i][0], xd, w0);
                    fma2(acc[i][1], xd, w1);
                    fma2(acc[i][2], xd, w2);
                }
            }
        }
        __syncthreads();
    }

#pragma unroll
    for (int i = 0; i < 4; i++) {
        int row = m0 + rg * 4 + i;
#pragma unroll
        for (int p = 0; p < 3; p++) {
            int tag = 2 * jg + p * 32;
            if (tag + 1 < NT) {
                float2 v = upk2(acc[i][p]);
                g_feats[(size_t)row * NT + tag]     = v.x + b_out[tag];
                g_feats[(size_t)row * NT + tag + 1] = v.y + b_out[tag + 1];
            }
        }
    }
}

// ---------------- kernel 4: Viterbi v2 (unchanged) ----------------
__global__ void __launch_bounds__(320) viterbi_kernel(
    const float* __restrict__ trans, float* __restrict__ out)
{
    const int b    = blockIdx.x;
    const int tid  = threadIdx.x;
    const int nt   = tid >> 2;
    const int s    = tid & 3;

    __shared__ float trans_s[NT * NT];
    __shared__ float fv0[NT], fv1[NT];
    __shared__ unsigned char bp[TT][NT];

    for (int i = tid; i < NT * NT; i += blockDim.x) trans_s[i] = trans[i];
    if (tid < NT) fv0[tid] = (tid == START_IDX) ? 0.0f : NEGV;
    __syncthreads();

    float tr[19];
    if (nt < NT) {
#pragma unroll
        for (int i = 0; i < 19; i++)
            tr[i] = trans_s[nt * NT + s * 19 + i];
    }

    const float* __restrict__ feats_b = g_feats + (size_t)b * TT * NT;

    for (int t = 0; t < TT; t++) {
        float* fv  = (t & 1) ? fv1 : fv0;
        float* fvn = (t & 1) ? fv0 : fv1;

        float best = -INFINITY;
        int arg = s * 19;
        if (nt < NT) {
#pragma unroll
            for (int i = 0; i < 19; i++) {
                float v = fv[s * 19 + i] + tr[i];
                if (v > best) { best = v; arg = s * 19 + i; }
            }
        }
#pragma unroll
        for (int dlt = 2; dlt >= 1; dlt >>= 1) {
            float ov = __shfl_down_sync(0xffffffffu, best, dlt);
            int   oa = __shfl_down_sync(0xffffffffu, arg,  dlt);
            if (ov > best) { best = ov; arg = oa; }
        }
        if (s == 0 && nt < NT) {
            fvn[nt] = best + feats_b[t * NT + nt];
            bp[t][nt] = (unsigned char)arg;
        }
        __syncthreads();
    }

    if (tid == 0) {
        float* fvF = fv0;
        float best = -INFINITY;
        int arg = 0;
        for (int j = 0; j < NT; j++) {
            float sc = fvF[j] + trans_s[STOP_IDX * NT + j];
            if (sc > best) { best = sc; arg = j; }
        }
        out[b] = best;
        float* po = out + BB + (size_t)b * TT;
        int tag = arg;
        po[TT - 1] = (float)tag;
        for (int t = TT - 1; t >= 1; t--) {
            tag = bp[t][tag];
            po[t - 1] = (float)tag;
        }
    }
}

// ---------------- launch ----------------
extern "C" void kernel_launch(void* const* d_in, const int* in_sizes, int n_in,
                              void* d_out, int out_size) {
    const int*   ids    = (const int*)  d_in[0];
    const float* emb    = (const float*)d_in[1];
    const float* Wih_f  = (const float*)d_in[2];
    const float* Whh_f  = (const float*)d_in[3];
    const float* bih_f  = (const float*)d_in[4];
    const float* bhh_f  = (const float*)d_in[5];
    const float* Wih_b  = (const float*)d_in[6];
    const float* Whh_b  = (const float*)d_in[7];
    const float* bih_b  = (const float*)d_in[8];
    const float* bhh_b  = (const float*)d_in[9];
    const float* h0     = (const float*)d_in[10];
    const float* c0     = (const float*)d_in[11];
    const float* W_out  = (const float*)d_in[12];
    const float* b_out  = (const float*)d_in[13];
    const float* trans  = (const float*)d_in[14];
    float* out = (float*)d_out;

    (void)in_sizes; (void)n_in; (void)out_size;

    // keeps the fixed ncu capture slot on lstm_rec
    noop_kernel<<<1, 32>>>();

    {
        const size_t total = (size_t)2 * 1024 * 256;
        transpose_whh_kernel<<<(unsigned)((total + 255) / 256), 256>>>(Whh_f, Whh_b);
    }
    {
        const int smem_bytes = (64 * 128 + 64 * 64) * 4;     // 48 KB -> 3 CTAs/SM
        cudaFuncSetAttribute(pregemm_kernel,
                             cudaFuncAttributeMaxDynamicSharedMemorySize, smem_bytes);
        dim3 grid(G4H / PGN, (BB * TT) / PGM, 2);
        pregemm_kernel<<<grid, 256, smem_bytes>>>(ids, emb, Wih_f, Wih_b,
                                                  bih_f, bhh_f, bih_b, bhh_b);
    }
    {
        // 112KB resident + 2x48KB staging + h bufs
        const int lstm_smem = (RK * 256 + 2 * 48 * 256 + 2 * 8 * HROW) * 4;
        cudaFuncSetAttribute(lstm_rec_kernel,
                             cudaFuncAttributeMaxDynamicSharedMemorySize, lstm_smem);
        lstm_rec_kernel<<<128, 256, lstm_smem>>>(h0, c0);
    }
    feats_kernel<<<(BB * TT) / 64, 256>>>(W_out, b_out);
    viterbi_kernel<<<BB, 320>>>(trans, out);
}